// round 6
// baseline (speedup 1.0000x reference)
#include <cuda_runtime.h>

#define BN 8
#define HH 512
#define WW 512
#define HWSZ (HH*WW)        // 262144 = 2^18
#define NPIX (BN*HWSZ)      // 2097152 = 2^21
#define THREADS 256
#define TS 64               // tile side
#define TPX (TS*TS)         // 4096 pixels / tile
#define NTILES (BN*(HH/TS)*(WW/TS))   // 512
#define NBORD (BN*2*7*WW)   // 57344 boundary pixels

// Scratch (device globals -- no allocation allowed)
__device__ int    g_par[2*NPIX];     // [0..NPIX) bg parents, [NPIX..2NPIX) fg parents (abs ids)
__device__ int    g_cnt[2*NPIX];     // component areas at global-root ids (only root slots valid)
__device__ int    g_lroot[2*NPIX];   // compact list: local-root abs ids
__device__ int    g_lcnt[2*NPIX];    // compact list: local counts
__device__ int    g_listn;           // list length
__device__ int    g_maxarea[2*BN];   // per-image max area: [0..BN)=bg, [BN..2BN)=fg
__device__ double g_S[6];            // S_fg[0..2], S_bg[0..2]
__device__ int    g_N[2];            // N_fg, N_bg

// ---------------- union-find (min-root, path-halving, race-safe) ----------------
__device__ __forceinline__ int uf_find(int* P, int x) {
    while (true) {
        int p = P[x];
        if (p == x) return x;
        int gp = P[p];
        if (gp == p) return p;
        atomicCAS(&P[x], p, gp);
        x = gp;
    }
}
__device__ __forceinline__ void uf_union(int* P, int a, int b) {
    int ra = uf_find(P, a);
    int rb = uf_find(P, b);
    while (ra != rb) {
        int hi = ra > rb ? ra : rb;
        int lo = (ra ^ rb) ^ hi;
        int old = atomicCAS(&P[hi], hi, lo);
        if (old == hi) return;
        ra = uf_find(P, old);
        rb = uf_find(P, lo);
    }
}

// ---------------- kernels ----------------

__global__ void k_zero() {
    int t = threadIdx.x;
    if (t == 0) g_listn = 0;
    if (t < 2*BN) g_maxarea[t] = 0;
    if (t < 6)    g_S[t] = 0.0;
    if (t < 2)    g_N[t] = 0;
}

// Per-tile CCL entirely in shared memory. Writes g_par for masked pixels and
// appends (local_root, local_count) to the compact global list.
__global__ void __launch_bounds__(THREADS) k_local(const float* __restrict__ cam) {
    __shared__ int      s_lab[TPX];
    __shared__ int      s_cnt[TPX];
    __shared__ unsigned s_mask[2][TPX/32];

    int blk = blockIdx.x;
    int b  = blk >> 6;
    int bi = blk & 63;
    int by = bi >> 3, bx = bi & 7;
    int base = b*HWSZ + (by*TS)*WW + bx*TS;
    int tid = threadIdx.x, lane = tid & 31;

    // build mask bitsets (warp ballots; lanes map to consecutive l)
    #pragma unroll
    for (int k = 0; k < TPX/THREADS; k++) {
        int l = tid + k*THREADS;
        float c = cam[base + (l>>6)*WW + (l&63)];
        unsigned mb = __ballot_sync(0xffffffffu, c >= 0.2f);
        unsigned mf = __ballot_sync(0xffffffffu, c >  0.6f);
        if (lane == 0) { s_mask[0][l>>5] = mb; s_mask[1][l>>5] = mf; }
    }
    __syncthreads();

    #pragma unroll
    for (int m = 0; m < 2; m++) {
        const unsigned* bits = s_mask[m];
        int gOff = m * NPIX;

        #pragma unroll
        for (int k = 0; k < TPX/THREADS; k++) {
            int l = tid + k*THREADS;
            s_lab[l] = l;
            s_cnt[l] = 0;
        }
        __syncthreads();

        // intra-tile unions (left, up) -- smem atomics only
        #pragma unroll
        for (int k = 0; k < TPX/THREADS; k++) {
            int l = tid + k*THREADS;
            if (!((bits[l>>5] >> (l&31)) & 1)) continue;
            if ((l & 63) && ((bits[(l-1)>>5] >> ((l-1)&31)) & 1))
                uf_union(s_lab, l, l-1);
            if (l >= TS && ((bits[(l-TS)>>5] >> ((l-TS)&31)) & 1))
                uf_union(s_lab, l, l-TS);
        }
        __syncthreads();

        // find roots (kept in registers) + local counts
        int roots[TPX/THREADS];
        #pragma unroll
        for (int k = 0; k < TPX/THREADS; k++) {
            int l = tid + k*THREADS;
            bool on = (bits[l>>5] >> (l&31)) & 1;
            int r = on ? uf_find(s_lab, l) : -1;
            roots[k] = r;
            if (on) atomicAdd(&s_cnt[r], 1);
        }
        __syncthreads();

        // emit parents + compact root list (warp-aggregated append)
        #pragma unroll
        for (int k = 0; k < TPX/THREADS; k++) {
            int l = tid + k*THREADS;
            int r = roots[k];
            bool on = r >= 0;
            int g = base + (l>>6)*WW + (l&63);
            if (on) {
                int gr = base + (r>>6)*WW + (r&63);
                g_par[gOff + g] = gOff + gr;
            }
            bool isroot = on && (r == l);
            unsigned bal = __ballot_sync(0xffffffffu, isroot);
            if (bal) {
                int basep = 0;
                if (lane == 0) basep = atomicAdd(&g_listn, __popc(bal));
                basep = __shfl_sync(0xffffffffu, basep, 0);
                if (isroot) {
                    int pos = basep + __popc(bal & ((1u << lane) - 1));
                    g_lroot[pos] = gOff + g;
                    g_lcnt[pos]  = s_cnt[l];
                }
            }
        }
        __syncthreads();
    }
}

// Cross-tile unions: only pixels on tile boundaries (global UF, ~160K unions)
__global__ void k_border(const float* __restrict__ cam) {
    int i = blockIdx.x * blockDim.x + threadIdx.x;
    if (i >= NBORD) return;
    int b   = i / (2*7*WW);
    int r   = i % (2*7*WW);
    int dir = r / (7*WW);
    int r2  = r % (7*WW);
    int line = r2 / WW;        // 0..6
    int pos  = r2 % WW;
    int t, tn;
    if (dir == 0) {            // horizontal edge: y = (line+1)*64, union with up
        int y = (line + 1) * TS;
        t = b*HWSZ + y*WW + pos; tn = t - WW;
    } else {                   // vertical edge: x = (line+1)*64, union with left
        int x = (line + 1) * TS;
        t = b*HWSZ + pos*WW + x; tn = t - 1;
    }
    float c0 = cam[t], c1 = cam[tn];
    if (c0 >= 0.2f && c1 >= 0.2f) {
        uf_union(g_par, t, tn);
        if (c0 > 0.6f && c1 > 0.6f) uf_union(g_par, NPIX + t, NPIX + tn);
    }
}

__global__ void k_zero_roots() {
    int n = g_listn;
    for (int i = blockIdx.x * blockDim.x + threadIdx.x; i < n; i += gridDim.x * blockDim.x)
        g_cnt[g_lroot[i]] = 0;
}

__global__ void k_accum() {
    int n = g_listn;
    for (int i = blockIdx.x * blockDim.x + threadIdx.x; i < n; i += gridDim.x * blockDim.x) {
        int e = g_lroot[i];
        int r = uf_find(g_par, e);
        g_par[e] = r;                 // compress: local roots point straight at global root
        atomicAdd(&g_cnt[r], g_lcnt[i]);
    }
}

__global__ void k_max() {
    int n = g_listn;
    for (int i = blockIdx.x * blockDim.x + threadIdx.x; i < n; i += gridDim.x * blockDim.x) {
        int e = g_lroot[i];
        if (g_par[e] == e) {          // global root
            int cnt = g_cnt[e];
            int idx = e & (NPIX - 1);
            int slot = (e >= NPIX ? BN : 0) + (idx >> 18);
            atomicMax(&g_maxarea[slot], cnt);
        }
    }
}

__device__ __forceinline__ int walk_root(const int* __restrict__ P, int x) {
    int p = P[x];
    while (true) { int q = P[p]; if (q == p) return p; p = q; }
}

__global__ void __launch_bounds__(THREADS) k_ce(const float* __restrict__ preds,
                                                const float* __restrict__ cam) {
    int t = blockIdx.x * blockDim.x + threadIdx.x;
    int b = t >> 18;
    int p = t & (HWSZ - 1);
    float c = cam[t];

    bool keep_bg = false, keep_fg = false;
    if (c >= 0.2f) {
        int r = walk_root(g_par, t);
        keep_bg = 2 * g_cnt[r] > g_maxarea[b];
        if (c > 0.6f) {
            int rf = walk_root(g_par, NPIX + t);
            keep_fg = 2 * g_cnt[rf] > g_maxarea[BN + b];
        }
    }
    bool vfg = keep_fg;
    bool vbg = !keep_bg;

    float s[6];
    #pragma unroll
    for (int i = 0; i < 3; i++) {
        const float* base = preds + (size_t)((i * BN + b) * 2) * HWSZ + p;
        float x0 = __ldg(base);
        float x1 = __ldg(base + HWSZ);
        float d  = x0 - x1;
        float l  = __logf(1.0f + __expf(-fabsf(d)));
        s[i]     = vfg ? (fmaxf(d,  0.0f) + l) : 0.0f;
        s[3 + i] = vbg ? (fmaxf(-d, 0.0f) + l) : 0.0f;
    }
    int nf = vfg ? 1 : 0, nb = vbg ? 1 : 0;

    #pragma unroll
    for (int o = 16; o; o >>= 1) {
        #pragma unroll
        for (int k = 0; k < 6; k++) s[k] += __shfl_down_sync(0xffffffffu, s[k], o);
        nf += __shfl_down_sync(0xffffffffu, nf, o);
        nb += __shfl_down_sync(0xffffffffu, nb, o);
    }
    __shared__ float sh[8][6];
    __shared__ int   shn[8][2];
    int w = threadIdx.x >> 5, lane = threadIdx.x & 31;
    if (lane == 0) {
        #pragma unroll
        for (int k = 0; k < 6; k++) sh[w][k] = s[k];
        shn[w][0] = nf; shn[w][1] = nb;
    }
    __syncthreads();
    if (threadIdx.x == 0) {
        #pragma unroll
        for (int i = 1; i < 8; i++) {
            #pragma unroll
            for (int k = 0; k < 6; k++) s[k] += sh[i][k];
            nf += shn[i][0]; nb += shn[i][1];
        }
        #pragma unroll
        for (int k = 0; k < 6; k++) atomicAdd(&g_S[k], (double)s[k]);
        atomicAdd(&g_N[0], nf);
        atomicAdd(&g_N[1], nb);
    }
}

__global__ void k_final(float* out) {
    double nf = g_N[0] < 1 ? 1.0 : (double)g_N[0];
    double nb = g_N[1] < 1 ? 1.0 : (double)g_N[1];
    double loss = 0.0;
    #pragma unroll
    for (int i = 0; i < 3; i++) loss += g_S[i] / nf + g_S[3 + i] / nb;
    out[0] = (float)loss;
}

// ---------------- launch ----------------
extern "C" void kernel_launch(void* const* d_in, const int* in_sizes, int n_in,
                              void* d_out, int out_size) {
    const float* preds = (const float*)d_in[0];
    const float* cams  = (const float*)d_in[1];
    if (n_in >= 2 && in_sizes[0] == NPIX) {   // defensive: swapped metadata order
        preds = (const float*)d_in[1];
        cams  = (const float*)d_in[0];
    }
    k_zero      <<<1, 32>>>();
    k_local     <<<NTILES, THREADS>>>(cams);
    k_border    <<<(NBORD + THREADS - 1) / THREADS, THREADS>>>(cams);
    k_zero_roots<<<592, THREADS>>>();
    k_accum     <<<592, THREADS>>>();
    k_max       <<<592, THREADS>>>();
    k_ce        <<<NPIX / THREADS, THREADS>>>(preds, cams);
    k_final     <<<1, 1>>>((float*)d_out);
}